// round 11
// baseline (speedup 1.0000x reference)
#include <cuda_runtime.h>
#include <cuda_bf16.h>
#include <math.h>
#include <stdint.h>

// ---------------------------------------------------------------------------
// ENL transformer block (Performer / FAVOR+), mma.sync bf16-split GEMMs
// with ldmatrix fragment loads and BK=32 double-buffered pipeline.
// B=8, C=256, N=4096 tokens/batch, F=256, MLP hidden=1024.
// ---------------------------------------------------------------------------

#define TOK   4096
#define BAT   8
#define DIMC  256
#define HID   1024
#define MTOT  (BAT * TOK)

typedef unsigned long long ull;

// ------------------------------ scratch ------------------------------------
__device__ float g_t  [(size_t)BAT * TOK * DIMC];
__device__ float g_h  [(size_t)BAT * TOK * DIMC];
__device__ float g_q  [(size_t)BAT * TOK * DIMC];
__device__ float g_k  [(size_t)BAT * TOK * DIMC];
__device__ float g_v  [(size_t)BAT * TOK * DIMC];
__device__ float g_qp [(size_t)BAT * TOK * DIMC];
__device__ float g_kp [(size_t)BAT * TOK * DIMC];
__device__ float g_m  [(size_t)BAT * TOK * HID];
__device__ float g_ctx[(size_t)BAT * DIMC * DIMC];
__device__ float g_ksum[BAT * DIMC];
__device__ float g_dq [(size_t)BAT * TOK];
__device__ float g_dk [(size_t)BAT * TOK];
__device__ float g_di [(size_t)BAT * TOK];

// ---------------------------- packed fp32x2 (k_atb) ------------------------
__device__ __forceinline__ void ffma2(ull& d, ull a, ull b) {
    asm("fma.rn.f32x2 %0, %1, %2, %0;" : "+l"(d) : "l"(a), "l"(b));
}
__device__ __forceinline__ ull pack2f(float x) {
    ull r; asm("mov.b64 %0, {%1, %1};" : "=l"(r) : "f"(x)); return r;
}
union U2 { ull u; float2 f; };

// ---------------------------- bf16 helpers ---------------------------------
__device__ __forceinline__ uint32_t bf2pack(float lo, float hi) {
    uint32_t r;
    asm("cvt.rn.bf16x2.f32 %0, %1, %2;" : "=r"(r) : "f"(hi), "f"(lo));
    return r;
}
__device__ __forceinline__ uint32_t smem_u32(const void* p) {
    uint32_t a;
    asm("{ .reg .u64 t; cvta.to.shared.u64 t, %1; cvt.u32.u64 %0, t; }"
        : "=r"(a) : "l"(p));
    return a;
}

// mma.sync m16n8k16 row.col f32 += bf16*bf16
__device__ __forceinline__ void mma16816v(float* c, const uint32_t* a,
                                          const uint32_t* b) {
    asm volatile(
        "mma.sync.aligned.m16n8k16.row.col.f32.bf16.bf16.f32 "
        "{%0,%1,%2,%3}, {%4,%5,%6,%7}, {%8,%9}, {%0,%1,%2,%3};"
        : "+f"(c[0]), "+f"(c[1]), "+f"(c[2]), "+f"(c[3])
        : "r"(a[0]), "r"(a[1]), "r"(a[2]), "r"(a[3]), "r"(b[0]), "r"(b[1]));
}

__device__ __forceinline__ void ldsm4(uint32_t r[4], uint32_t addr) {
    asm volatile(
        "ldmatrix.sync.aligned.m8n8.x4.shared.b16 {%0,%1,%2,%3}, [%4];"
        : "=r"(r[0]), "=r"(r[1]), "=r"(r[2]), "=r"(r[3]) : "r"(addr));
}

// Load B fragments for 2 n-tiles of 8 (16 W-rows) with one ldmatrix.x4.
// r0=(n0-7,klo) r1=(n8-15,klo) r2=(n0-7,khi) r3=(n8-15,khi)
// -> frag(n0-7) = {r0, r2}, frag(n8-15) = {r1, r3}
__device__ __forceinline__ void ldsm_b2(uint32_t b0[2], uint32_t b1[2],
                                        uint32_t addr) {
    uint32_t t[4];
    ldsm4(t, addr);
    b0[0] = t[0]; b0[1] = t[2];
    b1[0] = t[1]; b1[1] = t[3];
}

__device__ __forceinline__ void mma_all(float acc[16][4],
                                        uint32_t a[4][4], uint32_t b[4][2]) {
    #pragma unroll
    for (int mt = 0; mt < 4; mt++)
        #pragma unroll
        for (int nt = 0; nt < 4; nt++)
            mma16816v(acc[mt * 4 + nt], a[mt], b[nt]);
}

// ---------------------------------------------------------------------------
// mma.sync GEMM: C[M,N] = epi( A[M,K] @ W[N,K]^T ), bf16 hi/lo 3-pass split.
// CTA 128x128, BK=32, 8 warps (warp tile 64x32), ldmatrix frag loads,
// double-buffered dynamic smem (row stride 40 bf16 = 80B).
// modes: 0 bias | 1 bias+gelu | 2 bias+res | 3 featuremap | 4 res+aux*acc
// ---------------------------------------------------------------------------
// smem bf16-elem layout per buffer: Ah 0, Al 5120, Wh 10240, Wl 15360;
// buffer stride 20480 elems (40960 B). Total 81920 B.
#define GSM_BYTES 81920
#define RS 40            // row stride in bf16 elements (80 bytes)

__device__ __forceinline__ void split_store(__nv_bfloat16* hi, __nv_bfloat16* lo,
                                            int off, float4 v) {
    __nv_bfloat16 h0 = __float2bfloat16(v.x);
    __nv_bfloat16 h1 = __float2bfloat16(v.y);
    __nv_bfloat16 h2 = __float2bfloat16(v.z);
    __nv_bfloat16 h3 = __float2bfloat16(v.w);
    float l0 = v.x - __bfloat162float(h0);
    float l1 = v.y - __bfloat162float(h1);
    float l2 = v.z - __bfloat162float(h2);
    float l3 = v.w - __bfloat162float(h3);
    uint32_t hp0 = ((uint32_t)__bfloat16_as_ushort(h1) << 16) | __bfloat16_as_ushort(h0);
    uint32_t hp1 = ((uint32_t)__bfloat16_as_ushort(h3) << 16) | __bfloat16_as_ushort(h2);
    *(uint2*)(hi + off) = make_uint2(hp0, hp1);
    *(uint2*)(lo + off) = make_uint2(bf2pack(l0, l1), bf2pack(l2, l3));
}

__device__ __forceinline__ void stage_store(__nv_bfloat16* hi, __nv_bfloat16* lo,
                                            int row, int c0, const float4* st) {
    #pragma unroll
    for (int i = 0; i < 4; i++)
        split_store(hi, lo, row * RS + c0 + i * 4, st[i]);
}

__global__ void __launch_bounds__(256, 2) k_gemm_mma(
    const float* __restrict__ A, const float* __restrict__ W,
    const float* __restrict__ bias, float* __restrict__ Cout,
    int K, int N, int mode,
    const float* __restrict__ aux, const float* __restrict__ res,
    int wbatch)
{
    extern __shared__ __align__(16) char dsm[];
    __nv_bfloat16* sm = (__nv_bfloat16*)dsm;
    uint32_t sb = smem_u32(dsm);

    int tid = threadIdx.x;
    int lane = tid & 31, wid = tid >> 5;
    int wm = wid & 1, wn = wid >> 1;            // warp tile (wm*64, wn*32)
    int m0 = blockIdx.y * 128, n0 = blockIdx.x * 128;
    const float* Wp = W + (wbatch ? (size_t)(m0 / TOK) * (size_t)wbatch : 0);

    float acc[16][4];
    #pragma unroll
    for (int i = 0; i < 16; i++)
        #pragma unroll
        for (int j = 0; j < 4; j++) acc[i][j] = 0.f;

    // global staging map: thread -> (row, 16-float half-row)
    int row_ld = tid >> 1;
    int c0 = (tid & 1) * 16;
    const float* Arow = A  + (size_t)(m0 + row_ld) * K + c0;
    const float* Wrow = Wp + (size_t)(n0 + row_ld) * K + c0;

    // ldmatrix lane addressing:
    // lanes 0-7: rows 0-7 k-lo | 8-15: rows 8-15 k-lo
    // lanes 16-23: rows 0-7 k-hi | 24-31: rows 8-15 k-hi
    int ro   = ((lane >> 3) & 1) * 8 + (lane & 7);
    int kh16 = (lane >> 4) * 16;                 // byte offset for k-half
    uint32_t a_base = sb + (uint32_t)((wm * 64 + ro) * 80) + kh16;           // Ah
    uint32_t b_base = sb + 20480u + (uint32_t)((wn * 32 + ro) * 80) + kh16;  // Wh

    const int nc = K >> 5;

    // prologue: chunk 0 -> buffer 0
    {
        float4 st[4];
        #pragma unroll
        for (int i = 0; i < 4; i++) st[i] = *(const float4*)(Arow + i * 4);
        stage_store(sm, sm + 5120, row_ld, c0, st);
        #pragma unroll
        for (int i = 0; i < 4; i++) st[i] = *(const float4*)(Wrow + i * 4);
        stage_store(sm + 10240, sm + 15360, row_ld, c0, st);
    }
    __syncthreads();

    for (int c = 0; c < nc; c++) {
        int buf = c & 1;
        uint32_t bufB = (uint32_t)buf * 40960u;
        bool pf = (c + 1 < nc);
        float4 st[4];
        if (pf) {
            const float* p = Arow + (c + 1) * 32;
            #pragma unroll
            for (int i = 0; i < 4; i++) st[i] = *(const float4*)(p + i * 4);
        }
        #pragma unroll
        for (int ks = 0; ks < 2; ks++) {
            uint32_t ah[4][4], al[4][4], bb[4][2];
            uint32_t ab = a_base + bufB + ks * 32;
            uint32_t wb = b_base + bufB + ks * 32;
            #pragma unroll
            for (int mt = 0; mt < 4; mt++) ldsm4(ah[mt], ab + mt * 1280);
            #pragma unroll
            for (int np = 0; np < 2; np++)
                ldsm_b2(bb[2 * np], bb[2 * np + 1], wb + np * 1280);
            mma_all(acc, ah, bb);                       // Ahi * Whi
            #pragma unroll
            for (int mt = 0; mt < 4; mt++) ldsm4(al[mt], ab + 10240u + mt * 1280);
            mma_all(acc, al, bb);                       // Alo * Whi
            #pragma unroll
            for (int np = 0; np < 2; np++)
                ldsm_b2(bb[2 * np], bb[2 * np + 1], wb + 10240u + np * 1280);
            mma_all(acc, ah, bb);                       // Ahi * Wlo
            if (ks == 0 && pf) {
                int nb = buf ^ 1;
                stage_store(sm + nb * 20480, sm + nb * 20480 + 5120, row_ld, c0, st);
                const float* p = Wrow + (c + 1) * 32;
                #pragma unroll
                for (int i = 0; i < 4; i++) st[i] = *(const float4*)(p + i * 4);
            }
        }
        if (pf) {
            int nb = buf ^ 1;
            stage_store(sm + nb * 20480 + 10240, sm + nb * 20480 + 15360,
                        row_ld, c0, st);
        }
        __syncthreads();
    }

    // epilogue
    #pragma unroll
    for (int mt = 0; mt < 4; mt++) {
        #pragma unroll
        for (int half = 0; half < 2; half++) {
            int m = m0 + wm * 64 + mt * 16 + (lane >> 2) + half * 8;
            float am = (mode >= 3) ? aux[m] : 0.f;
            #pragma unroll
            for (int nt = 0; nt < 4; nt++) {
                int n = n0 + wn * 32 + nt * 8 + (lane & 3) * 2;
                float v0 = acc[mt * 4 + nt][half * 2 + 0];
                float v1 = acc[mt * 4 + nt][half * 2 + 1];
                if (mode == 0)      { v0 += bias[n]; v1 += bias[n + 1]; }
                else if (mode == 1) { v0 += bias[n]; v1 += bias[n + 1];
                                      v0 *= normcdff(v0); v1 *= normcdff(v1); }
                else if (mode == 2) { v0 += bias[n]     + res[(size_t)m * N + n];
                                      v1 += bias[n + 1] + res[(size_t)m * N + n + 1]; }
                else if (mode == 3) { v0 = 0.0625f * (expf(v0 - am) + 1e-4f);
                                      v1 = 0.0625f * (expf(v1 - am) + 1e-4f); }
                else                { v0 = res[(size_t)m * N + n]     + am * v0;
                                      v1 = res[(size_t)m * N + n + 1] + am * v1; }
                *(float2*)&Cout[(size_t)m * N + n] = make_float2(v0, v1);
            }
        }
    }
}

// ---------------------------------------------------------------------------
// K1: transpose [B,C,N] -> [B,N,C] + LayerNorm1 (t = shortcut, h = normed)
// ---------------------------------------------------------------------------
__global__ void __launch_bounds__(256) k_tr_ln(
    const float* __restrict__ x, const float* __restrict__ g,
    const float* __restrict__ bta, float* __restrict__ t, float* __restrict__ h)
{
    __shared__ float tile[32][257];
    int b  = blockIdx.y;
    int n0 = blockIdx.x * 32;
    const float* xb = x + (size_t)b * DIMC * TOK;
    int tx = threadIdx.x & 31, ty = threadIdx.x >> 5;
    #pragma unroll 4
    for (int cc = 0; cc < 32; cc++) {
        int c = cc * 8 + ty;
        tile[tx][c] = xb[(size_t)c * TOK + n0 + tx];
    }
    __syncthreads();
    for (int rep = 0; rep < 4; rep++) {
        int nl = ty + rep * 8;
        float v[8], s = 0.f, sq = 0.f;
        #pragma unroll
        for (int i = 0; i < 8; i++) {
            v[i] = tile[nl][tx + 32 * i];
            s += v[i]; sq += v[i] * v[i];
        }
        #pragma unroll
        for (int o = 16; o; o >>= 1) {
            s  += __shfl_xor_sync(~0u, s,  o);
            sq += __shfl_xor_sync(~0u, sq, o);
        }
        float mu  = s * (1.f / DIMC);
        float var = sq * (1.f / DIMC) - mu * mu;
        float inv = rsqrtf(var + 1e-5f);
        size_t base = ((size_t)b * TOK + n0 + nl) * DIMC;
        #pragma unroll
        for (int i = 0; i < 8; i++) {
            int c = tx + 32 * i;
            t[base + c] = v[i];
            h[base + c] = (v[i] - mu) * inv * g[c] + bta[c];
        }
    }
}

// ---------------------------------------------------------------------------
// LayerNorm2: warp per token.
// ---------------------------------------------------------------------------
__global__ void __launch_bounds__(256) k_ln(
    const float* __restrict__ t, const float* __restrict__ g,
    const float* __restrict__ bta, float* __restrict__ h)
{
    int tok  = blockIdx.x * 8 + (threadIdx.x >> 5);
    int lane = threadIdx.x & 31;
    const float* row = t + (size_t)tok * DIMC;
    float v[8], s = 0.f, sq = 0.f;
    #pragma unroll
    for (int i = 0; i < 8; i++) {
        v[i] = row[lane + 32 * i];
        s += v[i]; sq += v[i] * v[i];
    }
    #pragma unroll
    for (int o = 16; o; o >>= 1) {
        s  += __shfl_xor_sync(~0u, s,  o);
        sq += __shfl_xor_sync(~0u, sq, o);
    }
    float mu  = s * (1.f / DIMC);
    float var = sq * (1.f / DIMC) - mu * mu;
    float inv = rsqrtf(var + 1e-5f);
    float* hr = h + (size_t)tok * DIMC;
    #pragma unroll
    for (int i = 0; i < 8; i++) {
        int c = lane + 32 * i;
        hr[c] = (v[i] - mu) * inv * g[c] + bta[c];
    }
}

// ---------------------------------------------------------------------------
// L2-normalize q,k rows in place + diag = 0.5*||qn||^2.
// ---------------------------------------------------------------------------
__global__ void __launch_bounds__(256) k_norm(
    float* __restrict__ q, float* __restrict__ k,
    float* __restrict__ dq, float* __restrict__ dk)
{
    int tok  = blockIdx.x * 8 + (threadIdx.x >> 5);
    int lane = threadIdx.x & 31;
    for (int s2 = 0; s2 < 2; s2++) {
        float* row = (s2 == 0 ? q : k) + (size_t)tok * DIMC;
        float v[8], sq = 0.f;
        #pragma unroll
        for (int i = 0; i < 8; i++) {
            v[i] = row[lane + 32 * i];
            sq += v[i] * v[i];
        }
        #pragma unroll
        for (int o = 16; o; o >>= 1) sq += __shfl_xor_sync(~0u, sq, o);
        float nrm = sqrtf(sq);
        float sc  = 1.0f / fmaxf(nrm, 5e-5f);
        #pragma unroll
        for (int i = 0; i < 8; i++) row[lane + 32 * i] = v[i] * sc;
        if (lane == 0) (s2 == 0 ? dq : dk)[tok] = 0.5f * sq * sc * sc;
    }
}

// ---------------------------------------------------------------------------
// ctx^T[b][c][f] += sum_n v[b][n][c]*kp[b][n][f]  (fp32 FFMA2, ksplit=8)
// ---------------------------------------------------------------------------
__global__ void __launch_bounds__(256) k_atb(
    const float* __restrict__ V, const float* __restrict__ KP,
    float* __restrict__ CT)
{
    __shared__ __align__(16) float Vs[32][68];
    __shared__ __align__(16) float Ks[32][68];
    int b  = blockIdx.z >> 3;
    int ks = blockIdx.z & 7;
    int c0 = blockIdx.y * 64;
    int f0 = blockIdx.x * 64;
    const float* Vp = V  + (size_t)b * TOK * DIMC;
    const float* Kp = KP + (size_t)b * TOK * DIMC;
    int tid = threadIdx.x;
    int fc = tid & 15, r0 = tid >> 4;
    int tx = tid & 15, ty = tid >> 4;
    ull acc[4][2];
    #pragma unroll
    for (int i = 0; i < 4; i++) { acc[i][0] = 0ull; acc[i][1] = 0ull; }

    int nbeg = ks * (TOK / 8);
    for (int nt = 0; nt < TOK / 8; nt += 32) {
        #pragma unroll
        for (int rr = 0; rr < 32; rr += 16) {
            int n = nbeg + nt + r0 + rr;
            *(float4*)&Vs[r0 + rr][fc * 4] = *(const float4*)&Vp[(size_t)n * DIMC + c0 + fc * 4];
            *(float4*)&Ks[r0 + rr][fc * 4] = *(const float4*)&Kp[(size_t)n * DIMC + f0 + fc * 4];
        }
        __syncthreads();
        #pragma unroll
        for (int kk = 0; kk < 32; kk++) {
            float4 av = *(const float4*)&Vs[kk][ty * 4];
            ulonglong2 bq = *(const ulonglong2*)&Ks[kk][tx * 4];
            float a[4] = {av.x, av.y, av.z, av.w};
            #pragma unroll
            for (int i = 0; i < 4; i++) {
                ull ai = pack2f(a[i]);
                ffma2(acc[i][0], ai, bq.x);
                ffma2(acc[i][1], ai, bq.y);
            }
        }
        __syncthreads();
    }
    float* Cb = CT + (size_t)b * DIMC * DIMC;
    #pragma unroll
    for (int i = 0; i < 4; i++)
        #pragma unroll
        for (int j = 0; j < 2; j++) {
            U2 u; u.u = acc[i][j];
            atomicAdd(&Cb[(size_t)(c0 + ty * 4 + i) * DIMC + f0 + tx * 4 + 2 * j],     u.f.x);
            atomicAdd(&Cb[(size_t)(c0 + ty * 4 + i) * DIMC + f0 + tx * 4 + 2 * j + 1], u.f.y);
        }
}

// ---------------------------------------------------------------------------
// small helpers
// ---------------------------------------------------------------------------
__global__ void k_zero(float* __restrict__ p, int n)
{
    int i = blockIdx.x * 256 + threadIdx.x;
    if (i < n) p[i] = 0.f;
}

__global__ void __launch_bounds__(256) k_colsum(
    const float* __restrict__ kp, float* __restrict__ ksum)
{
    int b = blockIdx.y, ch = blockIdx.x;
    int f = threadIdx.x;
    const float* base = kp + ((size_t)b * TOK + ch * 128) * DIMC + f;
    float s = 0.f;
    #pragma unroll 8
    for (int i = 0; i < 128; i++) s += base[(size_t)i * DIMC];
    atomicAdd(&ksum[b * DIMC + f], s);
}

__global__ void __launch_bounds__(256) k_dinv(
    const float* __restrict__ qp, const float* __restrict__ ksum,
    float* __restrict__ di)
{
    int tok  = blockIdx.x * 8 + (threadIdx.x >> 5);
    int lane = threadIdx.x & 31;
    int b = tok >> 12;
    const float* row = qp + (size_t)tok * DIMC;
    const float* ks  = ksum + b * DIMC;
    float s = 0.f;
    #pragma unroll
    for (int i = 0; i < 8; i++) { int c = lane + 32 * i; s += row[c] * ks[c]; }
    #pragma unroll
    for (int o = 16; o; o >>= 1) s += __shfl_xor_sync(~0u, s, o);
    if (lane == 0) di[tok] = 1.0f / s;
}

__global__ void __launch_bounds__(256) k_out_tr(
    const float* __restrict__ t, float* __restrict__ out)
{
    __shared__ float tile[32][33];
    int b  = blockIdx.z;
    int n0 = blockIdx.x * 32;
    int c0 = blockIdx.y * 32;
    int tx = threadIdx.x & 31, ty = threadIdx.x >> 5;
    #pragma unroll
    for (int i = 0; i < 32; i += 8)
        tile[ty + i][tx] = t[((size_t)b * TOK + n0 + ty + i) * DIMC + c0 + tx];
    __syncthreads();
    #pragma unroll
    for (int i = 0; i < 32; i += 8)
        out[((size_t)b * DIMC + c0 + ty + i) * TOK + n0 + tx] = tile[tx][ty + i];
}

// ---------------------------------------------------------------------------
// host launch
// ---------------------------------------------------------------------------
extern "C" void kernel_launch(void* const* d_in, const int* in_sizes, int n_in,
                              void* d_out, int out_size)
{
    const float* x    = (const float*)d_in[0];
    const float* proj = (const float*)d_in[1];
    const float* wq   = (const float*)d_in[2];
    const float* bq   = (const float*)d_in[3];
    const float* wk   = (const float*)d_in[4];
    const float* bk   = (const float*)d_in[5];
    const float* wa   = (const float*)d_in[6];
    const float* ba   = (const float*)d_in[7];
    const float* g1   = (const float*)d_in[8];
    const float* b1   = (const float*)d_in[9];
    const float* g2   = (const float*)d_in[10];
    const float* b2   = (const float*)d_in[11];
    const float* w1   = (const float*)d_in[12];
    const float* fb1  = (const float*)d_in[13];
    const float* w2   = (const float*)d_in[14];
    const float* fb2  = (const float*)d_in[15];
    float* out = (float*)d_out;
    (void)in_sizes; (void)n_in; (void)out_size;

    float *t, *h, *q, *k, *v, *qp, *kp, *m, *ctx, *ksum, *dq, *dk, *di;
    cudaGetSymbolAddress((void**)&t,    g_t);
    cudaGetSymbolAddress((void**)&h,    g_h);
    cudaGetSymbolAddress((void**)&q,    g_q);
    cudaGetSymbolAddress((void**)&k,    g_k);
    cudaGetSymbolAddress((void**)&v,    g_v);
    cudaGetSymbolAddress((void**)&qp,   g_qp);
    cudaGetSymbolAddress((void**)&kp,   g_kp);
    cudaGetSymbolAddress((void**)&m,    g_m);
    cudaGetSymbolAddress((void**)&ctx,  g_ctx);
    cudaGetSymbolAddress((void**)&ksum, g_ksum);
    cudaGetSymbolAddress((void**)&dq,   g_dq);
    cudaGetSymbolAddress((void**)&dk,   g_dk);
    cudaGetSymbolAddress((void**)&di,   g_di);

    cudaFuncSetAttribute(k_gemm_mma,
                         cudaFuncAttributeMaxDynamicSharedMemorySize, GSM_BYTES);

    // 1. transpose + LN1
    k_tr_ln<<<dim3(TOK / 32, BAT), 256>>>(x, g1, b1, t, h);

    // 2. q, k, v projections (tensor cores)
    dim3 gproj(DIMC / 128, MTOT / 128);
    k_gemm_mma<<<gproj, 256, GSM_BYTES>>>(h, wq, bq, q, DIMC, DIMC, 0, nullptr, nullptr, 0);
    k_gemm_mma<<<gproj, 256, GSM_BYTES>>>(h, wk, bk, k, DIMC, DIMC, 0, nullptr, nullptr, 0);
    k_gemm_mma<<<gproj, 256, GSM_BYTES>>>(h, wa, ba, v, DIMC, DIMC, 0, nullptr, nullptr, 0);

    // 3. L2 normalize q,k + diag
    k_norm<<<MTOT / 8, 256>>>(q, k, dq, dk);

    // 4. FAVOR+ feature maps
    k_gemm_mma<<<gproj, 256, GSM_BYTES>>>(q, proj, nullptr, qp, DIMC, DIMC, 3, dq, nullptr, 0);
    k_gemm_mma<<<gproj, 256, GSM_BYTES>>>(k, proj, nullptr, kp, DIMC, DIMC, 3, dk, nullptr, 0);

    // 5. k_sum and ctx^T
    k_zero<<<(BAT * DIMC * DIMC + 255) / 256, 256>>>(ctx, BAT * DIMC * DIMC);
    k_zero<<<(BAT * DIMC + 255) / 256, 256>>>(ksum, BAT * DIMC);
    k_colsum<<<dim3(32, BAT), 256>>>(kp, ksum);
    k_atb<<<dim3(DIMC / 64, DIMC / 64, BAT * 8), 256>>>(v, kp, ctx);

    // 6. D_inv
    k_dinv<<<MTOT / 8, 256>>>(qp, ksum, di);

    // 7. out = res + D_inv * (qp @ ctx^T^T)  (per-batch W = ctx)
    k_gemm_mma<<<gproj, 256, GSM_BYTES>>>(qp, ctx, nullptr, t, DIMC, DIMC, 4, di, t, DIMC * DIMC);

    // 8. LN2 + MLP
    k_ln<<<MTOT / 8, 256>>>(t, g2, b2, h);
    k_gemm_mma<<<dim3(HID / 128, MTOT / 128), 256, GSM_BYTES>>>(
        h, w1, fb1, m, DIMC, HID, 1, nullptr, nullptr, 0);
    k_gemm_mma<<<dim3(DIMC / 128, MTOT / 128), 256, GSM_BYTES>>>(
        m, w2, fb2, t, HID, DIMC, 2, nullptr, t, 0);

    // 9. transpose back
    k_out_tr<<<dim3(TOK / 32, DIMC / 32, BAT), 256>>>(t, out);
}

// round 12
// speedup vs baseline: 1.0056x; 1.0056x over previous
#include <cuda_runtime.h>
#include <cuda_bf16.h>
#include <math.h>
#include <stdint.h>

// ---------------------------------------------------------------------------
// ENL transformer block (Performer / FAVOR+), mma.sync bf16-split GEMMs.
// Operands preconverted to bf16 hi/lo in global; cp.async staging; BK=32.
// B=8, C=256, N=4096 tokens/batch, F=256, MLP hidden=1024.
// ---------------------------------------------------------------------------

#define TOK   4096
#define BAT   8
#define DIMC  256
#define HID   1024
#define MTOT  (BAT * TOK)

typedef unsigned long long ull;
typedef __nv_bfloat16 bf16;

// ------------------------------ scratch ------------------------------------
// fp32
__device__ float g_t  [(size_t)MTOT * DIMC];
__device__ float g_q  [(size_t)MTOT * DIMC];
__device__ float g_k  [(size_t)MTOT * DIMC];
__device__ float g_v  [(size_t)MTOT * DIMC];
__device__ float g_qp [(size_t)MTOT * DIMC];
__device__ float g_kp [(size_t)MTOT * DIMC];
__device__ float g_ctx[(size_t)BAT * DIMC * DIMC];
__device__ float g_ksum[BAT * DIMC];
__device__ float g_dq [(size_t)MTOT];
__device__ float g_dk [(size_t)MTOT];
__device__ float g_di [(size_t)MTOT];
// bf16 hi/lo operand buffers
__device__ bf16 g_hh [(size_t)MTOT * DIMC], g_hl [(size_t)MTOT * DIMC];
__device__ bf16 g_qnh[(size_t)MTOT * DIMC], g_qnl[(size_t)MTOT * DIMC];
__device__ bf16 g_knh[(size_t)MTOT * DIMC], g_knl[(size_t)MTOT * DIMC];
__device__ bf16 g_qph[(size_t)MTOT * DIMC], g_qpl[(size_t)MTOT * DIMC];
__device__ bf16 g_h2h[(size_t)MTOT * DIMC], g_h2l[(size_t)MTOT * DIMC];
__device__ bf16 g_mh [(size_t)MTOT * HID],  g_ml [(size_t)MTOT * HID];
__device__ bf16 g_wqh[DIMC * DIMC], g_wql[DIMC * DIMC];
__device__ bf16 g_wkh[DIMC * DIMC], g_wkl[DIMC * DIMC];
__device__ bf16 g_wah[DIMC * DIMC], g_wal[DIMC * DIMC];
__device__ bf16 g_pjh[DIMC * DIMC], g_pjl[DIMC * DIMC];
__device__ bf16 g_w1h[HID * DIMC],  g_w1l[HID * DIMC];
__device__ bf16 g_w2h[DIMC * HID],  g_w2l[DIMC * HID];
__device__ bf16 g_cxh[BAT * DIMC * DIMC], g_cxl[BAT * DIMC * DIMC];

// ---------------------------- packed fp32x2 (k_atb) ------------------------
__device__ __forceinline__ void ffma2(ull& d, ull a, ull b) {
    asm("fma.rn.f32x2 %0, %1, %2, %0;" : "+l"(d) : "l"(a), "l"(b));
}
__device__ __forceinline__ ull pack2f(float x) {
    ull r; asm("mov.b64 %0, {%1, %1};" : "=l"(r) : "f"(x)); return r;
}
union U2 { ull u; float2 f; };

// ---------------------------- bf16 helpers ---------------------------------
__device__ __forceinline__ uint32_t bf2pack(float lo, float hi) {
    uint32_t r;
    asm("cvt.rn.bf16x2.f32 %0, %1, %2;" : "=r"(r) : "f"(hi), "f"(lo));
    return r;
}
__device__ __forceinline__ uint32_t smem_u32(const void* p) {
    uint32_t a;
    asm("{ .reg .u64 t; cvta.to.shared.u64 t, %1; cvt.u32.u64 %0, t; }"
        : "=r"(a) : "l"(p));
    return a;
}
__device__ __forceinline__ void split_one(float v, bf16* hp, bf16* lp) {
    bf16 h = __float2bfloat16(v);
    *hp = h;
    *lp = __float2bfloat16(v - __bfloat162float(h));
}

// mma.sync m16n8k16 row.col f32 += bf16*bf16
__device__ __forceinline__ void mma16816v(float* c, const uint32_t* a,
                                          const uint32_t* b) {
    asm volatile(
        "mma.sync.aligned.m16n8k16.row.col.f32.bf16.bf16.f32 "
        "{%0,%1,%2,%3}, {%4,%5,%6,%7}, {%8,%9}, {%0,%1,%2,%3};"
        : "+f"(c[0]), "+f"(c[1]), "+f"(c[2]), "+f"(c[3])
        : "r"(a[0]), "r"(a[1]), "r"(a[2]), "r"(a[3]), "r"(b[0]), "r"(b[1]));
}

#define CP16(dst, src) \
    asm volatile("cp.async.cg.shared.global [%0], [%1], 16;" \
                 :: "r"(dst), "l"(src))
#define CP_COMMIT() asm volatile("cp.async.commit_group;" ::: "memory")
#define CP_WAIT0()  asm volatile("cp.async.wait_group 0;" ::: "memory")

// ---------------------------------------------------------------------------
// GEMM: C[M,N] = epi( A[M,K] @ W[N,K]^T ), A/W given as bf16 hi+lo pairs.
// 3 passes: Ah*Wh + Ah*Wl + Al*Wh (lo*lo dropped).
// CTA 128x128, BK=32, 8 warps (warp tile 64x32), cp.async double buffer.
// smem elem layout / buffer: Ah 0, Al 5120, Wh 10240, Wl 15360; buf +20480.
// Row stride 40 elems (80B): r*20 mod 32 is a bank permutation.
// modes: 0 bias | 1 bias+gelu | 2 bias+res | 3 featuremap | 4 res+aux*acc
// ---------------------------------------------------------------------------
#define GSM_BYTES 81920
#define RS 40

__device__ __forceinline__ void ld_afrag(uint32_t af[4][4], const bf16* S,
                                         int ar, int ac) {
    #pragma unroll
    for (int mt = 0; mt < 4; mt++) {
        const bf16* p = S + (ar + mt * 16) * RS + ac;
        af[mt][0] = *(const uint32_t*)(p);
        af[mt][1] = *(const uint32_t*)(p + 8 * RS);
        af[mt][2] = *(const uint32_t*)(p + 8);
        af[mt][3] = *(const uint32_t*)(p + 8 * RS + 8);
    }
}
__device__ __forceinline__ void ld_bfrag(uint32_t bf[4][2], const bf16* S,
                                         int br, int ac) {
    #pragma unroll
    for (int nt = 0; nt < 4; nt++) {
        const bf16* p = S + (br + nt * 8) * RS + ac;
        bf[nt][0] = *(const uint32_t*)(p);
        bf[nt][1] = *(const uint32_t*)(p + 8);
    }
}
__device__ __forceinline__ void mma_all(float acc[16][4],
                                        uint32_t a[4][4], uint32_t b[4][2]) {
    #pragma unroll
    for (int mt = 0; mt < 4; mt++)
        #pragma unroll
        for (int nt = 0; nt < 4; nt++)
            mma16816v(acc[mt * 4 + nt], a[mt], b[nt]);
}

__global__ void __launch_bounds__(256, 2) k_gemm_mma(
    const bf16* __restrict__ Ah, const bf16* __restrict__ Al,
    const bf16* __restrict__ Wh, const bf16* __restrict__ Wl,
    const float* __restrict__ bias, float* __restrict__ outF,
    bf16* __restrict__ outHi, bf16* __restrict__ outLo,
    int K, int N, int mode,
    const float* __restrict__ aux, const float* __restrict__ res,
    int wbatch)
{
    extern __shared__ __align__(16) char dsm[];
    bf16* sm = (bf16*)dsm;
    uint32_t sb = smem_u32(dsm);

    int tid = threadIdx.x;
    int lane = tid & 31, wid = tid >> 5;
    int wm = wid & 1, wn = wid >> 1;
    int m0 = blockIdx.y * 128, n0 = blockIdx.x * 128;
    const bf16* Whp = Wh + (wbatch ? (size_t)(m0 / TOK) * (size_t)wbatch : 0);
    const bf16* Wlp = Wl + (wbatch ? (size_t)(m0 / TOK) * (size_t)wbatch : 0);

    float acc[16][4];
    #pragma unroll
    for (int i = 0; i < 16; i++)
        #pragma unroll
        for (int j = 0; j < 4; j++) acc[i][j] = 0.f;

    // cp.async staging map: thread -> two 16B segments
    int g0 = tid * 2;
    int row_s = g0 >> 2, seg = g0 & 3;          // seg in {0,2}
    size_t aoff = (size_t)(m0 + row_s) * K + seg * 8;
    size_t woff = (size_t)(n0 + row_s) * K + seg * 8;
    uint32_t dst0 = sb + (uint32_t)(row_s * 80 + seg * 16);

    int ar = wm * 64 + (lane >> 2);
    int br = wn * 32 + (lane >> 2);
    int lc = (lane & 3) * 2;

    const int nc = K >> 5;

    // prologue: chunk 0 -> buffer 0
    #pragma unroll
    for (int s = 0; s < 2; s++) {
        uint32_t d = dst0 + s * 16;
        CP16(d,          Ah  + aoff + s * 8);
        CP16(d + 10240u, Al  + aoff + s * 8);
        CP16(d + 20480u, Whp + woff + s * 8);
        CP16(d + 30720u, Wlp + woff + s * 8);
    }
    CP_COMMIT();
    CP_WAIT0();
    __syncthreads();

    for (int c = 0; c < nc; c++) {
        int buf = c & 1;
        bool pf = (c + 1 < nc);
        if (pf) {
            int kc = (c + 1) << 5;
            uint32_t db = dst0 + (buf ^ 1) * 40960u;
            #pragma unroll
            for (int s = 0; s < 2; s++) {
                uint32_t d = db + s * 16;
                CP16(d,          Ah  + aoff + kc + s * 8);
                CP16(d + 10240u, Al  + aoff + kc + s * 8);
                CP16(d + 20480u, Whp + woff + kc + s * 8);
                CP16(d + 30720u, Wlp + woff + kc + s * 8);
            }
            CP_COMMIT();
        }
        const bf16* Sb = sm + buf * 20480;
        #pragma unroll
        for (int ks = 0; ks < 2; ks++) {
            int ac = lc + ks * 16;
            uint32_t ah[4][4], bb[4][2];
            ld_afrag(ah, Sb, ar, ac);                 // A-hi
            ld_bfrag(bb, Sb + 10240, br, ac);         // W-hi
            mma_all(acc, ah, bb);                     // hh
            ld_bfrag(bb, Sb + 15360, br, ac);         // W-lo
            mma_all(acc, ah, bb);                     // h*lo
            ld_afrag(ah, Sb + 5120, ar, ac);          // A-lo (overwrite)
            ld_bfrag(bb, Sb + 10240, br, ac);         // W-hi
            mma_all(acc, ah, bb);                     // lo*h
        }
        if (pf) CP_WAIT0();
        __syncthreads();
    }

    // epilogue
    #pragma unroll
    for (int mt = 0; mt < 4; mt++) {
        #pragma unroll
        for (int half = 0; half < 2; half++) {
            int m = m0 + wm * 64 + mt * 16 + (lane >> 2) + half * 8;
            float am = (mode >= 3) ? aux[m] : 0.f;
            #pragma unroll
            for (int nt = 0; nt < 4; nt++) {
                int n = n0 + wn * 32 + nt * 8 + (lane & 3) * 2;
                float v0 = acc[mt * 4 + nt][half * 2 + 0];
                float v1 = acc[mt * 4 + nt][half * 2 + 1];
                if (mode == 0)      { v0 += bias[n]; v1 += bias[n + 1]; }
                else if (mode == 1) { v0 += bias[n]; v1 += bias[n + 1];
                                      v0 *= normcdff(v0); v1 *= normcdff(v1); }
                else if (mode == 2) { v0 += bias[n]     + res[(size_t)m * N + n];
                                      v1 += bias[n + 1] + res[(size_t)m * N + n + 1]; }
                else if (mode == 3) { v0 = 0.0625f * (expf(v0 - am) + 1e-4f);
                                      v1 = 0.0625f * (expf(v1 - am) + 1e-4f); }
                else                { v0 = res[(size_t)m * N + n]     + am * v0;
                                      v1 = res[(size_t)m * N + n + 1] + am * v1; }
                if (outF)
                    *(float2*)&outF[(size_t)m * N + n] = make_float2(v0, v1);
                if (outHi) {
                    bf16 h0 = __float2bfloat16(v0);
                    bf16 h1 = __float2bfloat16(v1);
                    uint32_t hp = ((uint32_t)__bfloat16_as_ushort(h1) << 16)
                                | __bfloat16_as_ushort(h0);
                    uint32_t lp = bf2pack(v0 - __bfloat162float(h0),
                                          v1 - __bfloat162float(h1));
                    *(uint32_t*)&outHi[(size_t)m * N + n] = hp;
                    *(uint32_t*)&outLo[(size_t)m * N + n] = lp;
                }
            }
        }
    }
}

// ---------------------------------------------------------------------------
// fp32 -> bf16 hi/lo converter (weights, ctx)
// ---------------------------------------------------------------------------
__global__ void k_cvt(const float* __restrict__ src, bf16* __restrict__ hi,
                      bf16* __restrict__ lo, int n)
{
    int i = blockIdx.x * 256 + threadIdx.x;
    if (i < n) split_one(src[i], &hi[i], &lo[i]);
}

// ---------------------------------------------------------------------------
// K1: transpose [B,C,N] -> [B,N,C]; t = shortcut fp32, h = LN1 as bf16 hi/lo
// ---------------------------------------------------------------------------
__global__ void __launch_bounds__(256) k_tr_ln(
    const float* __restrict__ x, const float* __restrict__ g,
    const float* __restrict__ bta, float* __restrict__ t,
    bf16* __restrict__ hh, bf16* __restrict__ hl)
{
    __shared__ float tile[32][257];
    int b  = blockIdx.y;
    int n0 = blockIdx.x * 32;
    const float* xb = x + (size_t)b * DIMC * TOK;
    int tx = threadIdx.x & 31, ty = threadIdx.x >> 5;
    #pragma unroll 4
    for (int cc = 0; cc < 32; cc++) {
        int c = cc * 8 + ty;
        tile[tx][c] = xb[(size_t)c * TOK + n0 + tx];
    }
    __syncthreads();
    for (int rep = 0; rep < 4; rep++) {
        int nl = ty + rep * 8;
        float v[8], s = 0.f, sq = 0.f;
        #pragma unroll
        for (int i = 0; i < 8; i++) {
            v[i] = tile[nl][tx + 32 * i];
            s += v[i]; sq += v[i] * v[i];
        }
        #pragma unroll
        for (int o = 16; o; o >>= 1) {
            s  += __shfl_xor_sync(~0u, s,  o);
            sq += __shfl_xor_sync(~0u, sq, o);
        }
        float mu  = s * (1.f / DIMC);
        float var = sq * (1.f / DIMC) - mu * mu;
        float inv = rsqrtf(var + 1e-5f);
        size_t base = ((size_t)b * TOK + n0 + nl) * DIMC;
        #pragma unroll
        for (int i = 0; i < 8; i++) {
            int c = tx + 32 * i;
            t[base + c] = v[i];
            float hv = (v[i] - mu) * inv * g[c] + bta[c];
            split_one(hv, &hh[base + c], &hl[base + c]);
        }
    }
}

// ---------------------------------------------------------------------------
// LayerNorm2: t fp32 -> h2 bf16 hi/lo
// ---------------------------------------------------------------------------
__global__ void __launch_bounds__(256) k_ln(
    const float* __restrict__ t, const float* __restrict__ g,
    const float* __restrict__ bta, bf16* __restrict__ hh, bf16* __restrict__ hl)
{
    int tok  = blockIdx.x * 8 + (threadIdx.x >> 5);
    int lane = threadIdx.x & 31;
    const float* row = t + (size_t)tok * DIMC;
    float v[8], s = 0.f, sq = 0.f;
    #pragma unroll
    for (int i = 0; i < 8; i++) {
        v[i] = row[lane + 32 * i];
        s += v[i]; sq += v[i] * v[i];
    }
    #pragma unroll
    for (int o = 16; o; o >>= 1) {
        s  += __shfl_xor_sync(~0u, s,  o);
        sq += __shfl_xor_sync(~0u, sq, o);
    }
    float mu  = s * (1.f / DIMC);
    float var = sq * (1.f / DIMC) - mu * mu;
    float inv = rsqrtf(var + 1e-5f);
    size_t base = (size_t)tok * DIMC;
    #pragma unroll
    for (int i = 0; i < 8; i++) {
        int c = lane + 32 * i;
        float hv = (v[i] - mu) * inv * g[c] + bta[c];
        split_one(hv, &hh[base + c], &hl[base + c]);
    }
}

// ---------------------------------------------------------------------------
// L2-normalize q,k -> bf16 hi/lo (qn, kn) + diag = 0.5*||qn||^2
// ---------------------------------------------------------------------------
__global__ void __launch_bounds__(256) k_norm(
    const float* __restrict__ q, const float* __restrict__ k,
    bf16* __restrict__ qh, bf16* __restrict__ ql,
    bf16* __restrict__ kh, bf16* __restrict__ kl,
    float* __restrict__ dq, float* __restrict__ dk)
{
    int tok  = blockIdx.x * 8 + (threadIdx.x >> 5);
    int lane = threadIdx.x & 31;
    for (int s2 = 0; s2 < 2; s2++) {
        const float* row = (s2 == 0 ? q : k) + (size_t)tok * DIMC;
        bf16* oh = (s2 == 0 ? qh : kh) + (size_t)tok * DIMC;
        bf16* ol = (s2 == 0 ? ql : kl) + (size_t)tok * DIMC;
        float v[8], sq = 0.f;
        #pragma unroll
        for (int i = 0; i < 8; i++) {
            v[i] = row[lane + 32 * i];
            sq += v[i] * v[i];
        }
        #pragma unroll
        for (int o = 16; o; o >>= 1) sq += __shfl_xor_sync(~0u, sq, o);
        float nrm = sqrtf(sq);
        float sc  = 1.0f / fmaxf(nrm, 5e-5f);
        #pragma unroll
        for (int i = 0; i < 8; i++) {
            int c = lane + 32 * i;
            split_one(v[i] * sc, &oh[c], &ol[c]);
        }
        if (lane == 0) (s2 == 0 ? dq : dk)[tok] = 0.5f * sq * sc * sc;
    }
}

// ---------------------------------------------------------------------------
// ctx^T[b][c][f] += sum_n v[b][n][c]*kp[b][n][f]  (fp32 FFMA2, ksplit=8)
// ---------------------------------------------------------------------------
__global__ void __launch_bounds__(256) k_atb(
    const float* __restrict__ V, const float* __restrict__ KP,
    float* __restrict__ CT)
{
    __shared__ __align__(16) float Vs[32][68];
    __shared__ __align__(16) float Ks[32][68];
    int b  = blockIdx.z >> 3;
    int ks = blockIdx.z & 7;
    int c0 = blockIdx.y * 64;
    int f0 = blockIdx.x * 64;
    const float* Vp = V  + (size_t)b * TOK * DIMC;
    const float* Kp = KP + (size_t)b * TOK * DIMC;
    int tid = threadIdx.x;
    int fc = tid & 15, r0 = tid >> 4;
    int tx = tid & 15, ty = tid >> 4;
    ull acc[4][2];
    #pragma unroll
    for (int i = 0; i < 4; i++) { acc[i][0] = 0ull; acc[i][1] = 0ull; }

    int nbeg = ks * (TOK / 8);
    for (int nt = 0; nt < TOK / 8; nt += 32) {
        #pragma unroll
        for (int rr = 0; rr < 32; rr += 16) {
            int n = nbeg + nt + r0 + rr;
            *(float4*)&Vs[r0 + rr][fc * 4] = *(const float4*)&Vp[(size_t)n * DIMC + c0 + fc * 4];
            *(float4*)&Ks[r0 + rr][fc * 4] = *(const float4*)&Kp[(size_t)n * DIMC + f0 + fc * 4];
        }
        __syncthreads();
        #pragma unroll
        for (int kk = 0; kk < 32; kk++) {
            float4 av = *(const float4*)&Vs[kk][ty * 4];
            ulonglong2 bq = *(const ulonglong2*)&Ks[kk][tx * 4];
            float a[4] = {av.x, av.y, av.z, av.w};
            #pragma unroll
            for (int i = 0; i < 4; i++) {
                ull ai = pack2f(a[i]);
                ffma2(acc[i][0], ai, bq.x);
                ffma2(acc[i][1], ai, bq.y);
            }
        }
        __syncthreads();
    }
    float* Cb = CT + (size_t)b * DIMC * DIMC;
    #pragma unroll
    for (int i = 0; i < 4; i++)
        #pragma unroll
        for (int j = 0; j < 2; j++) {
            U2 u; u.u = acc[i][j];
            atomicAdd(&Cb[(size_t)(c0 + ty * 4 + i) * DIMC + f0 + tx * 4 + 2 * j],     u.f.x);
            atomicAdd(&Cb[(size_t)(c0 + ty * 4 + i) * DIMC + f0 + tx * 4 + 2 * j + 1], u.f.y);
        }
}

// ---------------------------------------------------------------------------
// small helpers
// ---------------------------------------------------------------------------
__global__ void k_zero(float* __restrict__ p, int n)
{
    int i = blockIdx.x * 256 + threadIdx.x;
    if (i < n) p[i] = 0.f;
}

__global__ void __launch_bounds__(256) k_colsum(
    const float* __restrict__ kp, float* __restrict__ ksum)
{
    int b = blockIdx.y, ch = blockIdx.x;
    int f = threadIdx.x;
    const float* base = kp + ((size_t)b * TOK + ch * 128) * DIMC + f;
    float s = 0.f;
    #pragma unroll 8
    for (int i = 0; i < 128; i++) s += base[(size_t)i * DIMC];
    atomicAdd(&ksum[b * DIMC + f], s);
}

__global__ void __launch_bounds__(256) k_dinv(
    const float* __restrict__ qp, const float* __restrict__ ksum,
    float* __restrict__ di)
{
    int tok  = blockIdx.x * 8 + (threadIdx.x >> 5);
    int lane = threadIdx.x & 31;
    int b = tok >> 12;
    const float* row = qp + (size_t)tok * DIMC;
    const float* ks  = ksum + b * DIMC;
    float s = 0.f;
    #pragma unroll
    for (int i = 0; i < 8; i++) { int c = lane + 32 * i; s += row[c] * ks[c]; }
    #pragma unroll
    for (int o = 16; o; o >>= 1) s += __shfl_xor_sync(~0u, s, o);
    if (lane == 0) di[tok] = 1.0f / s;
}

__global__ void __launch_bounds__(256) k_out_tr(
    const float* __restrict__ t, float* __restrict__ out)
{
    __shared__ float tile[32][33];
    int b  = blockIdx.z;
    int n0 = blockIdx.x * 32;
    int c0 = blockIdx.y * 32;
    int tx = threadIdx.x & 31, ty = threadIdx.x >> 5;
    #pragma unroll
    for (int i = 0; i < 32; i += 8)
        tile[ty + i][tx] = t[((size_t)b * TOK + n0 + ty + i) * DIMC + c0 + tx];
    __syncthreads();
    #pragma unroll
    for (int i = 0; i < 32; i += 8)
        out[((size_t)b * DIMC + c0 + ty + i) * TOK + n0 + tx] = tile[tx][ty + i];
}

// ---------------------------------------------------------------------------
// host launch
// ---------------------------------------------------------------------------
#define SYM(var, sym) cudaGetSymbolAddress((void**)&var, sym)

extern "C" void kernel_launch(void* const* d_in, const int* in_sizes, int n_in,
                              void* d_out, int out_size)
{
    const float* x    = (const float*)d_in[0];
    const float* proj = (const float*)d_in[1];
    const float* wq   = (const float*)d_in[2];
    const float* bq   = (const float*)d_in[3];
    const float* wk   = (const float*)d_in[4];
    const float* bk   = (const float*)d_in[5];
    const float* wa   = (const float*)d_in[6];
    const float* ba   = (const float*)d_in[7];
    const float* g1   = (const float*)d_in[8];
    const float* b1   = (const float*)d_in[9];
    const float* g2   = (const float*)d_in[10];
    const float* b2   = (const float*)d_in[11];
    const float* w1   = (const float*)d_in[12];
    const float* fb1  = (const float*)d_in[13];
    const float* w2   = (const float*)d_in[14];
    const float* fb2  = (const float*)d_in[15];
    float* out = (float*)d_out;
    (void)in_sizes; (void)n_in; (void)out_size;

    float *t, *q, *k, *v, *qp, *kp, *ctx, *ksum, *dq, *dk, *di;
    bf16 *hh, *hl, *qnh, *qnl, *knh, *knl, *qph, *qpl, *h2h, *h2l, *mh, *ml;
    bf16 *wqh, *wql, *wkh, *wkl, *wah, *wal, *pjh, *pjl;
    bf16 *w1h, *w1l, *w2h, *w2l, *cxh, *cxl;
    SYM(t, g_t);   SYM(q, g_q);   SYM(k, g_k);   SYM(v, g_v);
    SYM(qp, g_qp); SYM(kp, g_kp); SYM(ctx, g_ctx); SYM(ksum, g_ksum);
    SYM(dq, g_dq); SYM(dk, g_dk); SYM(di, g_di);
    SYM(hh, g_hh);   SYM(hl, g_hl);
    SYM(qnh, g_qnh); SYM(qnl, g_qnl); SYM(knh, g_knh); SYM(knl, g_knl);
    SYM(qph, g_qph); SYM(qpl, g_qpl); SYM(h2h, g_h2h); SYM(h2l, g_h2l);
    SYM(mh, g_mh);   SYM(ml, g_ml);
    SYM(wqh, g_wqh); SYM(wql, g_wql); SYM(wkh, g_wkh); SYM(wkl, g_wkl);
    SYM(wah, g_wah); SYM(wal, g_wal); SYM(pjh, g_pjh); SYM(pjl, g_pjl);
    SYM(w1h, g_w1h); SYM(w1l, g_w1l); SYM(w2h, g_w2h); SYM(w2l, g_w2l);
    SYM(cxh, g_cxh); SYM(cxl, g_cxl);

    cudaFuncSetAttribute(k_gemm_mma,
                         cudaFuncAttributeMaxDynamicSharedMemorySize, GSM_BYTES);

    // 0. weight conversions
    k_cvt<<<DIMC * DIMC / 256, 256>>>(wq, wqh, wql, DIMC * DIMC);
    k_cvt<<<DIMC * DIMC / 256, 256>>>(wk, wkh, wkl, DIMC * DIMC);
    k_cvt<<<DIMC * DIMC / 256, 256>>>(wa, wah, wal, DIMC * DIMC);
    k_cvt<<<DIMC * DIMC / 256, 256>>>(proj, pjh, pjl, DIMC * DIMC);
    k_cvt<<<HID * DIMC / 256, 256>>>(w1, w1h, w1l, HID * DIMC);
    k_cvt<<<HID * DIMC / 256, 256>>>(w2, w2h, w2l, HID * DIMC);

    // 1. transpose + LN1
    k_tr_ln<<<dim3(TOK / 32, BAT), 256>>>(x, g1, b1, t, hh, hl);

    // 2. q, k, v projections
    dim3 gproj(DIMC / 128, MTOT / 128);
    k_gemm_mma<<<gproj, 256, GSM_BYTES>>>(hh, hl, wqh, wql, bq, q, nullptr, nullptr,
                                          DIMC, DIMC, 0, nullptr, nullptr, 0);
    k_gemm_mma<<<gproj, 256, GSM_BYTES>>>(hh, hl, wkh, wkl, bk, k, nullptr, nullptr,
                                          DIMC, DIMC, 0, nullptr, nullptr, 0);
    k_gemm_mma<<<gproj, 256, GSM_BYTES>>>(hh, hl, wah, wal, ba, v, nullptr, nullptr,
                                          DIMC, DIMC, 0, nullptr, nullptr, 0);

    // 3. L2 normalize q,k -> bf16 hi/lo + diag
    k_norm<<<MTOT / 8, 256>>>(q, k, qnh, qnl, knh, knl, dq, dk);

    // 4. FAVOR+ feature maps (qp also as hi/lo for the out GEMM)
    k_gemm_mma<<<gproj, 256, GSM_BYTES>>>(qnh, qnl, pjh, pjl, nullptr, qp, qph, qpl,
                                          DIMC, DIMC, 3, dq, nullptr, 0);
    k_gemm_mma<<<gproj, 256, GSM_BYTES>>>(knh, knl, pjh, pjl, nullptr, kp, nullptr, nullptr,
                                          DIMC, DIMC, 3, dk, nullptr, 0);

    // 5. k_sum and ctx^T, then ctx -> bf16 hi/lo
    k_zero<<<(BAT * DIMC * DIMC + 255) / 256, 256>>>(ctx, BAT * DIMC * DIMC);
    k_zero<<<(BAT * DIMC + 255) / 256, 256>>>(ksum, BAT * DIMC);
    k_colsum<<<dim3(32, BAT), 256>>>(kp, ksum);
    k_atb<<<dim3(DIMC / 64, DIMC / 64, BAT * 8), 256>>>(v, kp, ctx);
    k_cvt<<<BAT * DIMC * DIMC / 256, 256>>>(ctx, cxh, cxl, BAT * DIMC * DIMC);

    // 6. D_inv
    k_dinv<<<MTOT / 8, 256>>>(qp, ksum, di);

    // 7. out = res + D_inv * (qp @ ctx^T^T)  (per-batch W = ctx)
    k_gemm_mma<<<gproj, 256, GSM_BYTES>>>(qph, qpl, cxh, cxl, nullptr, t, nullptr, nullptr,
                                          DIMC, DIMC, 4, di, t, DIMC * DIMC);

    // 8. LN2 + MLP
    k_ln<<<MTOT / 8, 256>>>(t, g2, b2, h2h, h2l);
    k_gemm_mma<<<dim3(HID / 128, MTOT / 128), 256, GSM_BYTES>>>(
        h2h, h2l, w1h, w1l, fb1, nullptr, mh, ml, DIMC, HID, 1, nullptr, nullptr, 0);
    k_gemm_mma<<<dim3(DIMC / 128, MTOT / 128), 256, GSM_BYTES>>>(
        mh, ml, w2h, w2l, fb2, t, nullptr, nullptr, HID, DIMC, 2, nullptr, t, 0);

    // 9. transpose back
    k_out_tr<<<dim3(TOK / 32, DIMC / 32, BAT), 256>>>(t, out);
}